// round 17
// baseline (speedup 1.0000x reference)
#include <cuda_runtime.h>

#define N_USR 50000
#define N_ENT 100000
#define DD 64
#define NE 1000000
#define NEI 500000

// ---- scratch (device globals; no allocation allowed) ----
__device__ __align__(16) float g_P[N_ENT * DD];       // P = src @ W_Q (256-B rows)
__device__ __align__(16) float g_eL1[N_ENT * DD];     // entity emb after layer 1
__device__ __align__(16) float g_esum[N_ENT * DD];    // running sum of entity embs
__device__ __align__(16) float g_agg[N_ENT * DD];     // per-layer accumulator
__device__ __align__(16) float g_den[N_ENT * 2];      // softmax denominators

// ---- init: esum = entity_emb; d_out user region = user_emb; zero agg/den ----
__global__ void k_init(const float4* __restrict__ ue, const float4* __restrict__ ee,
                       float4* __restrict__ uout) {
    int i = blockIdx.x * blockDim.x + threadIdx.x;
    if (i < N_ENT * DD / 4) {
        ((float4*)g_esum)[i] = ee[i];
        ((float4*)g_agg)[i] = make_float4(0.f, 0.f, 0.f, 0.f);
    }
    if (i < N_USR * DD / 4) uout[i] = ue[i];
    if (i < N_ENT * 2 / 4)
        ((float4*)g_den)[i] = make_float4(0.f, 0.f, 0.f, 0.f);
}

// ---- P = src @ W_Q ; warp handles 4 rows, lane owns 2 output cols ----
__global__ void k_gemm(const float* __restrict__ ein, int layer,
                       const float* __restrict__ W) {
    const float* src = (layer == 0) ? ein : g_eL1;
    __shared__ float sW[DD * DD];
    for (int i = threadIdx.x; i < DD * DD; i += 256) sW[i] = W[i];
    __syncthreads();
    int warp = threadIdx.x >> 5, lane = threadIdx.x & 31;
    int r0 = (blockIdx.x * 8 + warp) * 4;
    if (r0 >= N_ENT) return;
    const float* e0 = &src[(size_t)r0 * DD];
    float acc[8] = {0.f, 0.f, 0.f, 0.f, 0.f, 0.f, 0.f, 0.f};
    #pragma unroll 4
    for (int k = 0; k < DD; k += 4) {
        float4 a[4];
        #pragma unroll
        for (int rr = 0; rr < 4; rr++) a[rr] = *(const float4*)&e0[rr * DD + k];
        #pragma unroll
        for (int j = 0; j < 4; j++) {
            float2 wv = *(const float2*)&sW[(k + j) * DD + lane * 2];
            #pragma unroll
            for (int rr = 0; rr < 4; rr++) {
                float av = (j == 0) ? a[rr].x : (j == 1) ? a[rr].y : (j == 2) ? a[rr].z : a[rr].w;
                acc[rr * 2]     += av * wv.x;
                acc[rr * 2 + 1] += av * wv.y;
            }
        }
    }
    #pragma unroll
    for (int rr = 0; rr < 4; rr++)
        *(float2*)&g_P[(size_t)(r0 + rr) * DD + lane * 2] =
            make_float2(acc[rr * 2], acc[rr * 2 + 1]);
}

// ---- user aggregation: uout += w * src[item]  (16 lanes per inter-edge) ----
__global__ void k_user(const int* __restrict__ iu, const int* __restrict__ ii,
                       const float* __restrict__ w, const float* __restrict__ ein,
                       int layer, float* __restrict__ uout) {
    const float* src = (layer == 0) ? ein : g_eL1;
    int gid = blockIdx.x * blockDim.x + threadIdx.x;
    int e = gid >> 4, hl = gid & 15;
    if (e >= NEI) return;
    int u = __ldg(&iu[e]), it = __ldg(&ii[e]);
    float ww = __ldg(&w[e]);
    float4 v = *(const float4*)&src[(size_t)it * DD + hl * 4];
    atomicAdd((float4*)&uout[(size_t)u * DD + hl * 4],
              make_float4(v.x * ww, v.y * ww, v.z * ww, v.w * ww));
}

// ---- edge-parallel fused pass (unsorted -> spread atomics), R6-proven form:
//      16 lanes/edge, lane hl owns dims 4hl..4hl+3; lanes 0-7 head0, 8-15 head1.
//      score -> exp -> den RED + float4 RED of ex*(v*rel) into g_agg ----
__global__ void k_edge(const int* __restrict__ head, const int* __restrict__ tail,
                       const int* __restrict__ et, const float* __restrict__ rel,
                       const float* __restrict__ ein, int layer) {
    const float* src = (layer == 0) ? ein : g_eL1;
    int gid = blockIdx.x * blockDim.x + threadIdx.x;
    int e = gid >> 4, hl = gid & 15;
    if (e >= NE) return;
    int h = __ldg(&head[e]), t = __ldg(&tail[e]), r = __ldg(&et[e]) - 1;
    float4 ph = *(const float4*)&g_P[(size_t)h * DD + hl * 4];
    float4 pt = *(const float4*)&g_P[(size_t)t * DD + hl * 4];
    float4 rl = __ldg((const float4*)&rel[r * DD + hl * 4]);
    float p = ph.x * pt.x * rl.x + ph.y * pt.y * rl.y +
              ph.z * pt.z * rl.z + ph.w * pt.w * rl.w;
    p += __shfl_xor_sync(0xffffffffu, p, 1);
    p += __shfl_xor_sync(0xffffffffu, p, 2);
    p += __shfl_xor_sync(0xffffffffu, p, 4);
    const float inv = 0.17677669529663688f;  // 1/sqrt(32)
    float ex = __expf(p * inv);
    if ((hl & 7) == 0)
        atomicAdd(&g_den[h * 2 + (hl >> 3)], ex);
    float4 v = *(const float4*)&src[(size_t)t * DD + hl * 4];
    float4 o = make_float4(ex * v.x * rl.x, ex * v.y * rl.y,
                           ex * v.z * rl.z, ex * v.w * rl.w);
    atomicAdd((float4*)&g_agg[(size_t)h * DD + hl * 4], o);
}

// ---- per-row finalize: agg/den -> L2 norm; esum; re-zero agg/den;
//      layer 1 writes final entity mean straight to d_out ----
__global__ void k_update(int layer, float* __restrict__ eout) {
    int row = (blockIdx.x * blockDim.x + threadIdx.x) >> 5;
    int lane = threadIdx.x & 31;
    if (row >= N_ENT) return;
    float2* ap = (float2*)&g_agg[(size_t)row * DD + lane * 2];
    float2 a = *ap;
    *ap = make_float2(0.f, 0.f);
    float d = g_den[row * 2 + (lane >> 4)];
    if (lane < 2) g_den[row * 2 + lane] = 0.f;
    float invd = (d > 0.f) ? (1.f / d) : 0.f;
    a.x *= invd; a.y *= invd;
    float ss = a.x * a.x + a.y * a.y;
    #pragma unroll
    for (int m = 1; m < 32; m <<= 1) ss += __shfl_xor_sync(0xffffffffu, ss, m);
    float nrm = 1.f / fmaxf(sqrtf(ss), 1e-12f);
    float ex0 = a.x * nrm, ey0 = a.y * nrm;
    float2* es = (float2*)&g_esum[(size_t)row * DD + lane * 2];
    float2 o = *es;
    if (layer == 0) {
        *(float2*)&g_eL1[(size_t)row * DD + lane * 2] = make_float2(ex0, ey0);
        *es = make_float2(o.x + ex0, o.y + ey0);
    } else {
        const float th = 1.f / 3.f;
        *(float2*)&eout[(size_t)row * DD + lane * 2] =
            make_float2((o.x + ex0) * th, (o.y + ey0) * th);
    }
}

// ---- scale user output by 1/3 ----
__global__ void k_ufinal(float4* __restrict__ uout) {
    int i = blockIdx.x * blockDim.x + threadIdx.x;
    if (i < N_USR * DD / 4) {
        const float th = 1.f / 3.f;
        float4 v = uout[i];
        uout[i] = make_float4(v.x * th, v.y * th, v.z * th, v.w * th);
    }
}

extern "C" void kernel_launch(void* const* d_in, const int* in_sizes, int n_in,
                              void* d_out, int out_size) {
    // inputs: layers_num, user_emb, entity_emb, inter_edge, inter_edge_w,
    //         edge_index, edge_type, relation_emb, W_Q
    const float* user_emb = (const float*)d_in[1];
    const float* ent_emb  = (const float*)d_in[2];
    const int*   inter    = (const int*)d_in[3];
    const float* iw       = (const float*)d_in[4];
    const int*   eidx     = (const int*)d_in[5];
    const int*   etype    = (const int*)d_in[6];
    const float* rel      = (const float*)d_in[7];
    const float* WQ       = (const float*)d_in[8];
    const int* head = eidx;
    const int* tail = eidx + NE;
    const int* iu = inter;
    const int* ii = inter + NEI;
    float* out = (float*)d_out;
    float* out_ent = out + (size_t)N_USR * DD;

    const int T = 256;
    const int nE4 = N_ENT * DD / 4;  // 1.6M

    k_init<<<(nE4 + T - 1) / T, T>>>((const float4*)user_emb, (const float4*)ent_emb,
                                     (float4*)out);
    for (int l = 0; l < 2; l++) {
        k_gemm<<<N_ENT / 32, 256>>>(ent_emb, l, WQ);
        // k_user launched BEFORE k_edge (independent) so k_edge is the 4th
        // kernel overall -> ncu's -s 5 -c 1 (with 2 harness pre-launches)
        // finally captures the dominant kernel.
        k_user<<<NEI * 16 / T, T>>>(iu, ii, iw, ent_emb, l, out);
        k_edge<<<NE * 16 / T, T>>>(head, tail, etype, rel, ent_emb, l);
        k_update<<<(N_ENT * 32 + T - 1) / T, T>>>(l, out_ent);
    }
    k_ufinal<<<(N_USR * DD / 4 + T - 1) / T, T>>>((float4*)out);
}